// round 1
// baseline (speedup 1.0000x reference)
#include <cuda_runtime.h>

#define N_PTS   524288
#define TBITS   19
#define TSIZE   (1u << TBITS)
#define TMASK   (TSIZE - 1u)
#define BLOCK   128
#define SMEM_FLOATS 13544
#define SMEM_BYTES  (SMEM_FLOATS * 4)

// Packed dual-FMA: d = a*b + c elementwise on float2 (sm_103a f32x2 pipe, 2 MACs/instr)
__device__ __forceinline__ float2 ffma2(float2 a, float2 b, float2 c) {
    float2 d;
    asm("fma.rn.f32x2 %0, %1, %2, %3;"
        : "=l"(reinterpret_cast<unsigned long long&>(d))
        : "l"(reinterpret_cast<unsigned long long&>(a)),
          "l"(reinterpret_cast<unsigned long long&>(b)),
          "l"(reinterpret_cast<unsigned long long&>(c)));
    return d;
}

// floor(16 * 64^(l/15)) for l=0..15 (matches numpy float64 computation)
__constant__ float c_scale[16] = {
    16.f, 21.f, 27.f, 36.f, 48.f, 64.f, 84.f, 111.f,
    147.f, 194.f, 256.f, 337.f, 445.f, 588.f, 776.f, 1024.f
};

__global__ void ngp_fused_kernel(
    const float*  __restrict__ pos,  const float* __restrict__ dir,
    const float2* __restrict__ tab,
    const float* __restrict__ w0, const float* __restrict__ b0,
    const float* __restrict__ w1, const float* __restrict__ b1,
    const float* __restrict__ w2, const float* __restrict__ b2,
    const float* __restrict__ wr, const float* __restrict__ br,
    const float* __restrict__ wc, const float* __restrict__ bc,
    const float* __restrict__ wd, const float* __restrict__ bd,
    float* __restrict__ out)
{
    extern __shared__ float sm[];
    // Weight layout (all pair-packed regions at even float offsets => 8B aligned)
    float2* s_wp0 = (float2*)(sm + 0);        // [64 out][16 in-pairs]
    float2* s_wp1 = (float2*)(sm + 2048);     // [64 out][32 in-pairs]
    float2* s_wp2 = (float2*)(sm + 6144);     // [64 out][32 in-pairs]
    float2* s_wrb = (float2*)(sm + 10240);    // [32 out][32 base-pairs] (wr rows 27..90)
    float*  s_wrd = sm + 12288;               // [27][32] (wr rows 0..26, row-major copy)
    float*  s_wc  = sm + 13152;               // [32][3]
    float2* s_wd  = (float2*)(sm + 13248);    // [32 pairs]
    float*  s_b0  = sm + 13312;               // 64
    float*  s_b1  = sm + 13376;               // 64
    float*  s_b2  = sm + 13440;               // 64
    float*  s_br  = sm + 13504;               // 32
    float*  s_bc  = sm + 13536;               // 3 (+pad)
    float*  s_bd  = sm + 13540;               // 1

    const int t = threadIdx.x;
    for (int k = t; k < 64 * 16; k += BLOCK) {
        int o = k >> 4, i2 = k & 15;
        s_wp0[k] = make_float2(w0[(2 * i2) * 64 + o], w0[(2 * i2 + 1) * 64 + o]);
    }
    for (int k = t; k < 64 * 32; k += BLOCK) {
        int o = k >> 5, i2 = k & 31;
        s_wp1[k] = make_float2(w1[(2 * i2) * 64 + o], w1[(2 * i2 + 1) * 64 + o]);
        s_wp2[k] = make_float2(w2[(2 * i2) * 64 + o], w2[(2 * i2 + 1) * 64 + o]);
    }
    for (int k = t; k < 32 * 32; k += BLOCK) {
        int o = k >> 5, i2 = k & 31;
        s_wrb[k] = make_float2(wr[(27 + 2 * i2) * 32 + o], wr[(27 + 2 * i2 + 1) * 32 + o]);
    }
    for (int k = t; k < 27 * 32; k += BLOCK) s_wrd[k] = wr[k];
    for (int k = t; k < 96; k += BLOCK) s_wc[k] = wc[k];
    for (int k = t; k < 32; k += BLOCK) s_wd[k] = make_float2(wd[2 * k], wd[2 * k + 1]);
    for (int k = t; k < 64; k += BLOCK) { s_b0[k] = b0[k]; s_b1[k] = b1[k]; s_b2[k] = b2[k]; }
    for (int k = t; k < 32; k += BLOCK) s_br[k] = br[k];
    if (t < 3) s_bc[t] = bc[t];
    if (t == 0) s_bd[0] = bd[0];
    __syncthreads();

    const int i = blockIdx.x * BLOCK + t;
    if (i >= N_PTS) return;

    const float px = pos[3 * i], py = pos[3 * i + 1], pz = pos[3 * i + 2];

    // ---------------- Hash-grid encode: enc[l] = (feat0, feat1) per level ----------------
    float2 enc[16];
    #pragma unroll
    for (int l = 0; l < 16; l++) {
        const float sc = c_scale[l];
        const float sx = px * sc, sy = py * sc, sz = pz * sc;
        const float fx = floorf(sx), fy = floorf(sy), fz = floorf(sz);
        const float ox = sx - fx, oy = sy - fy, oz = sz - fz;
        const unsigned hx0 = (unsigned)(int)fx;                              // prime 1
        const unsigned hx1 = (unsigned)(int)ceilf(sx);
        const unsigned hy0 = (unsigned)(int)fy * 2654435761u;
        const unsigned hy1 = (unsigned)(int)ceilf(sy) * 2654435761u;
        const unsigned hz0 = (unsigned)(int)fz * 805459861u;
        const unsigned hz1 = (unsigned)(int)ceilf(sz) * 805459861u;
        const unsigned lvl = ((unsigned)l) << TBITS;

        float2 tv[8];
        #pragma unroll
        for (int c = 0; c < 8; c++) {
            unsigned h = ((c & 1) ? hx1 : hx0) ^ ((c & 2) ? hy1 : hy0) ^ ((c & 4) ? hz1 : hz0);
            tv[c] = __ldg(&tab[(h & TMASK) + lvl]);
        }
        const float wx0 = 1.f - ox, wy0 = 1.f - oy, wz0 = 1.f - oz;
        float2 a = make_float2(0.f, 0.f);
        #pragma unroll
        for (int c = 0; c < 8; c++) {
            float w = ((c & 1) ? ox : wx0) * ((c & 2) ? oy : wy0) * ((c & 4) ? oz : wz0);
            a.x = fmaf(w, tv[c].x, a.x);
            a.y = fmaf(w, tv[c].y, a.y);
        }
        enc[l] = a;
    }

    // ---------------- Layer 0: 32 -> 64, relu ----------------
    float2 h0[32];
    #pragma unroll
    for (int o2 = 0; o2 < 32; o2++) {
        float2 aa = make_float2(0.f, 0.f), ab = make_float2(0.f, 0.f);
        const float2* wA = s_wp0 + (2 * o2) * 16;
        const float2* wB = s_wp0 + (2 * o2 + 1) * 16;
        #pragma unroll
        for (int i2 = 0; i2 < 16; i2++) {
            aa = ffma2(enc[i2], wA[i2], aa);
            ab = ffma2(enc[i2], wB[i2], ab);
        }
        h0[o2] = make_float2(fmaxf(aa.x + aa.y + s_b0[2 * o2],     0.f),
                             fmaxf(ab.x + ab.y + s_b0[2 * o2 + 1], 0.f));
    }

    // ---------------- Layer 1: 64 -> 64, relu ----------------
    float2 h1[32];
    #pragma unroll
    for (int o2 = 0; o2 < 32; o2++) {
        float2 aa = make_float2(0.f, 0.f), ab = make_float2(0.f, 0.f);
        const float2* wA = s_wp1 + (2 * o2) * 32;
        const float2* wB = s_wp1 + (2 * o2 + 1) * 32;
        #pragma unroll
        for (int i2 = 0; i2 < 32; i2++) {
            aa = ffma2(h0[i2], wA[i2], aa);
            ab = ffma2(h0[i2], wB[i2], ab);
        }
        h1[o2] = make_float2(fmaxf(aa.x + aa.y + s_b1[2 * o2],     0.f),
                             fmaxf(ab.x + ab.y + s_b1[2 * o2 + 1], 0.f));
    }

    // ---------------- Layer 2: 64 -> 64, linear (base) ----------------
    float2 bp[32];
    #pragma unroll
    for (int o2 = 0; o2 < 32; o2++) {
        float2 aa = make_float2(0.f, 0.f), ab = make_float2(0.f, 0.f);
        const float2* wA = s_wp2 + (2 * o2) * 32;
        const float2* wB = s_wp2 + (2 * o2 + 1) * 32;
        #pragma unroll
        for (int i2 = 0; i2 < 32; i2++) {
            aa = ffma2(h1[i2], wA[i2], aa);
            ab = ffma2(h1[i2], wB[i2], ab);
        }
        bp[o2] = make_float2(aa.x + aa.y + s_b2[2 * o2],
                             ab.x + ab.y + s_b2[2 * o2 + 1]);
    }

    // ---------------- Direction NeRF encode ----------------
    const float dx = dir[3 * i], dy = dir[3 * i + 1], dz = dir[3 * i + 2];
    float dsin[12], dcos[12];
    {
        const float fr[4] = {1.f, 2.5198421f, 6.3496042f, 16.f}; // 2^linspace(0,4,4)
        const float tx = 6.2831855f * dx, ty = 6.2831855f * dy, tz = 6.2831855f * dz;
        #pragma unroll
        for (int k = 0; k < 4; k++) {
            sincosf(tx * fr[k], &dsin[0 + k], &dcos[0 + k]);
            sincosf(ty * fr[k], &dsin[4 + k], &dcos[4 + k]);
            sincosf(tz * fr[k], &dsin[8 + k], &dcos[8 + k]);
        }
    }

    // ---------------- RGB head: concat(enc_dir[27], base[64]) @ wr -> 32 ----------------
    float rgbh[32];
    #pragma unroll
    for (int o = 0; o < 32; o++) {
        float acc = s_br[o];
        #pragma unroll
        for (int j = 0; j < 12; j++) acc = fmaf(dsin[j], s_wrd[j * 32 + o], acc);
        #pragma unroll
        for (int j = 0; j < 12; j++) acc = fmaf(dcos[j], s_wrd[(12 + j) * 32 + o], acc);
        acc = fmaf(dx, s_wrd[24 * 32 + o], acc);
        acc = fmaf(dy, s_wrd[25 * 32 + o], acc);
        acc = fmaf(dz, s_wrd[26 * 32 + o], acc);
        float2 a2 = make_float2(0.f, 0.f);
        const float2* wv = s_wrb + o * 32;
        #pragma unroll
        for (int i2 = 0; i2 < 32; i2++) a2 = ffma2(bp[i2], wv[i2], a2);
        rgbh[o] = acc + a2.x + a2.y;
    }

    // rgb = sigmoid(rgbh @ wc + bc)
    float rgb[3];
    #pragma unroll
    for (int c = 0; c < 3; c++) {
        float acc = s_bc[c];
        #pragma unroll
        for (int o = 0; o < 32; o++) acc = fmaf(rgbh[o], s_wc[o * 3 + c], acc);
        rgb[c] = 1.f / (1.f + expf(-acc));
    }

    // density = softplus(base @ wd + bd)
    float2 a2 = make_float2(0.f, 0.f);
    #pragma unroll
    for (int i2 = 0; i2 < 32; i2++) a2 = ffma2(bp[i2], s_wd[i2], a2);
    const float xd = a2.x + a2.y + s_bd[0];
    const float dens = fmaxf(xd, 0.f) + log1pf(expf(-fabsf(xd)));

    float* op = out + 4 * i;
    op[0] = rgb[0]; op[1] = rgb[1]; op[2] = rgb[2]; op[3] = dens;
}

extern "C" void kernel_launch(void* const* d_in, const int* in_sizes, int n_in,
                              void* d_out, int out_size) {
    (void)in_sizes; (void)n_in; (void)out_size;
    const float*  pos = (const float*)d_in[0];
    const float*  dir = (const float*)d_in[1];
    const float2* tab = (const float2*)d_in[2];
    const float *w0 = (const float*)d_in[3],  *b0 = (const float*)d_in[4];
    const float *w1 = (const float*)d_in[5],  *b1 = (const float*)d_in[6];
    const float *w2 = (const float*)d_in[7],  *b2 = (const float*)d_in[8];
    const float *wr = (const float*)d_in[9],  *br = (const float*)d_in[10];
    const float *wc = (const float*)d_in[11], *bc = (const float*)d_in[12];
    const float *wd = (const float*)d_in[13], *bd = (const float*)d_in[14];
    float* out = (float*)d_out;

    cudaFuncSetAttribute(ngp_fused_kernel,
                         cudaFuncAttributeMaxDynamicSharedMemorySize, SMEM_BYTES);
    ngp_fused_kernel<<<N_PTS / BLOCK, BLOCK, SMEM_BYTES>>>(
        pos, dir, tab, w0, b0, w1, b1, w2, b2, wr, br, wc, bc, wd, bd, out);
}

// round 2
// speedup vs baseline: 1.0665x; 1.0665x over previous
#include <cuda_runtime.h>

#define N_PTS   524288
#define TBITS   19
#define TSIZE   (1u << TBITS)
#define TMASK   (TSIZE - 1u)
#define BLOCK   128
#define SMEM_FLOATS 13576
#define SMEM_BYTES  (SMEM_FLOATS * 4)

// Packed dual-FMA: d = a*b + c elementwise on float2 (sm_103a f32x2 pipe)
__device__ __forceinline__ float2 ffma2(float2 a, float2 b, float2 c) {
    float2 d;
    asm("fma.rn.f32x2 %0, %1, %2, %3;"
        : "=l"(reinterpret_cast<unsigned long long&>(d))
        : "l"(reinterpret_cast<unsigned long long&>(a)),
          "l"(reinterpret_cast<unsigned long long&>(b)),
          "l"(reinterpret_cast<unsigned long long&>(c)));
    return d;
}

// floor(16 * 64^(l/15)) for l=0..15
__constant__ float c_scale[16] = {
    16.f, 21.f, 27.f, 36.f, 48.f, 64.f, 84.f, 111.f,
    147.f, 194.f, 256.f, 337.f, 445.f, 588.f, 776.f, 1024.f
};

__global__ void ngp_fused_kernel(
    const float*  __restrict__ pos,  const float* __restrict__ dir,
    const float2* __restrict__ tab,
    const float* __restrict__ w0, const float* __restrict__ b0,
    const float* __restrict__ w1, const float* __restrict__ b1,
    const float* __restrict__ w2, const float* __restrict__ b2,
    const float* __restrict__ wr, const float* __restrict__ br,
    const float* __restrict__ wc, const float* __restrict__ bc,
    const float* __restrict__ wd, const float* __restrict__ bd,
    float* __restrict__ out)
{
    extern __shared__ float sm[];
    // All float4 regions at 16B-aligned float offsets
    float4* s_w0  = (float4*)(sm + 0);      // [64 out][8  q]  q packs in-feats 4q..4q+3
    float4* s_w1  = (float4*)(sm + 2048);   // [64 out][16 q]
    float4* s_w2  = (float4*)(sm + 6144);   // [64 out][16 q]
    float4* s_wrb = (float4*)(sm + 10240);  // [32 out][16 q]  (wr rows 27..90)
    float4* s_wrd = (float4*)(sm + 12288);  // [32 out][7  q]  (wr rows 0..26, padded to 28)
    float4* s_wc  = (float4*)(sm + 13184);  // [3  c ][8  q]
    float4* s_wd  = (float4*)(sm + 13280);  // [16 q]
    float*  s_b0  = sm + 13344;             // 64
    float*  s_b1  = sm + 13408;             // 64
    float*  s_b2  = sm + 13472;             // 64
    float*  s_br  = sm + 13536;             // 32
    float*  s_bc  = sm + 13568;             // 3 (+pad)
    float*  s_bd  = sm + 13572;             // 1

    const int t = threadIdx.x;
    for (int k = t; k < 64 * 8; k += BLOCK) {               // w0: in-major [32][64]
        int o = k >> 3, q = k & 7;
        s_w0[k] = make_float4(w0[(4*q  )*64 + o], w0[(4*q+1)*64 + o],
                              w0[(4*q+2)*64 + o], w0[(4*q+3)*64 + o]);
    }
    for (int k = t; k < 64 * 16; k += BLOCK) {              // w1,w2: [64][64]
        int o = k >> 4, q = k & 15;
        s_w1[k] = make_float4(w1[(4*q  )*64 + o], w1[(4*q+1)*64 + o],
                              w1[(4*q+2)*64 + o], w1[(4*q+3)*64 + o]);
        s_w2[k] = make_float4(w2[(4*q  )*64 + o], w2[(4*q+1)*64 + o],
                              w2[(4*q+2)*64 + o], w2[(4*q+3)*64 + o]);
    }
    for (int k = t; k < 32 * 16; k += BLOCK) {              // wr rows 27..90
        int o = k >> 4, q = k & 15;
        s_wrb[k] = make_float4(wr[(27+4*q  )*32 + o], wr[(27+4*q+1)*32 + o],
                               wr[(27+4*q+2)*32 + o], wr[(27+4*q+3)*32 + o]);
    }
    for (int k = t; k < 32 * 7; k += BLOCK) {               // wr rows 0..26 (+pad)
        int o = k / 7, q = k % 7;
        float a = wr[(4*q  )*32 + o];
        float b = wr[(4*q+1)*32 + o];
        float c = wr[(4*q+2)*32 + o];
        float d = (q == 6) ? 0.f : wr[(4*q+3)*32 + o];
        s_wrd[k] = make_float4(a, b, c, d);
    }
    for (int k = t; k < 3 * 8; k += BLOCK) {                // wc: [32][3] -> [3][32]
        int c = k >> 3, q = k & 7;
        s_wc[k] = make_float4(wc[(4*q  )*3 + c], wc[(4*q+1)*3 + c],
                              wc[(4*q+2)*3 + c], wc[(4*q+3)*3 + c]);
    }
    for (int k = t; k < 16; k += BLOCK)
        s_wd[k] = make_float4(wd[4*k], wd[4*k+1], wd[4*k+2], wd[4*k+3]);
    for (int k = t; k < 64; k += BLOCK) { s_b0[k] = b0[k]; s_b1[k] = b1[k]; s_b2[k] = b2[k]; }
    for (int k = t; k < 32; k += BLOCK) s_br[k] = br[k];
    if (t < 3) s_bc[t] = bc[t];
    if (t == 0) s_bd[0] = bd[0];
    __syncthreads();

    const int i = blockIdx.x * BLOCK + t;
    if (i >= N_PTS) return;

    const float px = pos[3 * i], py = pos[3 * i + 1], pz = pos[3 * i + 2];

    // ---------------- Hash-grid encode ----------------
    float2 enc[16];
    #pragma unroll
    for (int l = 0; l < 16; l++) {
        const float sc = c_scale[l];
        const float sx = px * sc, sy = py * sc, sz = pz * sc;
        const float fx = floorf(sx), fy = floorf(sy), fz = floorf(sz);
        const float ox = sx - fx, oy = sy - fy, oz = sz - fz;
        const unsigned hx0 = (unsigned)(int)fx;                 // prime = 1
        const unsigned hx1 = (unsigned)(int)ceilf(sx);
        const unsigned hy0 = (unsigned)(int)fy * 2654435761u;
        const unsigned hy1 = (unsigned)(int)ceilf(sy) * 2654435761u;
        const unsigned hz0 = (unsigned)(int)fz * 805459861u;
        const unsigned hz1 = (unsigned)(int)ceilf(sz) * 805459861u;
        const unsigned lvl = ((unsigned)l) << TBITS;
        const float wx0 = 1.f - ox, wy0 = 1.f - oy, wz0 = 1.f - oz;

        float2 a = make_float2(0.f, 0.f);
        #pragma unroll
        for (int p = 0; p < 4; p++) {   // (y,z) corner combo; x corners paired
            const unsigned hyz = ((p & 1) ? hy1 : hy0) ^ ((p & 2) ? hz1 : hz0);
            const unsigned i0 = (hx0 ^ hyz) & TMASK;
            const unsigned i1 = (hx1 ^ hyz) & TMASK;
            // x-prime is 1: when hx0 even, i1 == i0^1 -> same aligned float4
            const float4 q = __ldg((const float4*)(tab + ((i0 & ~1u) + lvl)));
            const float2 lo = make_float2(q.x, q.y);
            const float2 hi = make_float2(q.z, q.w);
            float2 e0 = (i0 & 1u) ? hi : lo;
            float2 e1;
            if (i1 == (i0 ^ 1u)) {
                e1 = (i0 & 1u) ? lo : hi;
            } else {
                e1 = __ldg(&tab[i1 + lvl]);
            }
            const float wyz = ((p & 1) ? oy : wy0) * ((p & 2) ? oz : wz0);
            const float w0f = wx0 * wyz, w1f = ox * wyz;
            a = ffma2(make_float2(w0f, w0f), e0, a);
            a = ffma2(make_float2(w1f, w1f), e1, a);
        }
        enc[l] = a;
    }

    // ---------------- Layer 0: 32 -> 64, relu ----------------
    float2 h0[32];
    #pragma unroll
    for (int o = 0; o < 64; o++) {
        float2 a = make_float2(0.f, 0.f);
        const float4* wrow = s_w0 + o * 8;
        #pragma unroll
        for (int q = 0; q < 8; q++) {
            const float4 v = wrow[q];
            a = ffma2(enc[2*q],     make_float2(v.x, v.y), a);
            a = ffma2(enc[2*q + 1], make_float2(v.z, v.w), a);
        }
        const float r = fmaxf(a.x + a.y + s_b0[o], 0.f);
        if (o & 1) h0[o >> 1].y = r; else h0[o >> 1].x = r;
    }

    // ---------------- Layer 1: 64 -> 64, relu ----------------
    float2 h1[32];
    #pragma unroll
    for (int o = 0; o < 64; o++) {
        float2 a = make_float2(0.f, 0.f);
        const float4* wrow = s_w1 + o * 16;
        #pragma unroll
        for (int q = 0; q < 16; q++) {
            const float4 v = wrow[q];
            a = ffma2(h0[2*q],     make_float2(v.x, v.y), a);
            a = ffma2(h0[2*q + 1], make_float2(v.z, v.w), a);
        }
        const float r = fmaxf(a.x + a.y + s_b1[o], 0.f);
        if (o & 1) h1[o >> 1].y = r; else h1[o >> 1].x = r;
    }

    // ---------------- Layer 2: 64 -> 64, linear (base) ----------------
    float2 bp[32];
    #pragma unroll
    for (int o = 0; o < 64; o++) {
        float2 a = make_float2(0.f, 0.f);
        const float4* wrow = s_w2 + o * 16;
        #pragma unroll
        for (int q = 0; q < 16; q++) {
            const float4 v = wrow[q];
            a = ffma2(h1[2*q],     make_float2(v.x, v.y), a);
            a = ffma2(h1[2*q + 1], make_float2(v.z, v.w), a);
        }
        const float r = a.x + a.y + s_b2[o];
        if (o & 1) bp[o >> 1].y = r; else bp[o >> 1].x = r;
    }

    // ---------------- Direction NeRF encode -> dvec[28] ----------------
    const float dx = dir[3 * i], dy = dir[3 * i + 1], dz = dir[3 * i + 2];
    float dvec[28];
    {
        const float fr[4] = {1.f, 2.5198421f, 6.3496042f, 16.f};
        const float tx = 6.2831855f * dx, ty = 6.2831855f * dy, tz = 6.2831855f * dz;
        #pragma unroll
        for (int k = 0; k < 4; k++) {
            sincosf(tx * fr[k], &dvec[0 + k],  &dvec[12 + k]);
            sincosf(ty * fr[k], &dvec[4 + k],  &dvec[16 + k]);
            sincosf(tz * fr[k], &dvec[8 + k],  &dvec[20 + k]);
        }
        dvec[24] = dx; dvec[25] = dy; dvec[26] = dz; dvec[27] = 0.f;
    }

    // ---------------- RGB head: concat(enc_dir[27], base[64]) @ wr -> 32 ----------------
    float rgbh[32];
    #pragma unroll
    for (int o = 0; o < 32; o++) {
        float acc = s_br[o];
        const float4* wdrow = s_wrd + o * 7;
        #pragma unroll
        for (int q = 0; q < 7; q++) {
            const float4 v = wdrow[q];
            acc = fmaf(dvec[4*q], v.x, acc);
            acc = fmaf(dvec[4*q+1], v.y, acc);
            acc = fmaf(dvec[4*q+2], v.z, acc);
            acc = fmaf(dvec[4*q+3], v.w, acc);
        }
        float2 a2 = make_float2(0.f, 0.f);
        const float4* wbrow = s_wrb + o * 16;
        #pragma unroll
        for (int q = 0; q < 16; q++) {
            const float4 v = wbrow[q];
            a2 = ffma2(bp[2*q],     make_float2(v.x, v.y), a2);
            a2 = ffma2(bp[2*q + 1], make_float2(v.z, v.w), a2);
        }
        rgbh[o] = acc + a2.x + a2.y;
    }

    // rgb = sigmoid(rgbh @ wc + bc)
    float4 res;
    {
        float accs[3];
        #pragma unroll
        for (int c = 0; c < 3; c++) {
            float acc = s_bc[c];
            const float4* wcrow = s_wc + c * 8;
            #pragma unroll
            for (int q = 0; q < 8; q++) {
                const float4 v = wcrow[q];
                acc = fmaf(rgbh[4*q],   v.x, acc);
                acc = fmaf(rgbh[4*q+1], v.y, acc);
                acc = fmaf(rgbh[4*q+2], v.z, acc);
                acc = fmaf(rgbh[4*q+3], v.w, acc);
            }
            accs[c] = 1.f / (1.f + expf(-acc));
        }
        res.x = accs[0]; res.y = accs[1]; res.z = accs[2];
    }

    // density = softplus(base @ wd + bd)
    {
        float2 a2 = make_float2(0.f, 0.f);
        #pragma unroll
        for (int q = 0; q < 16; q++) {
            const float4 v = s_wd[q];
            a2 = ffma2(bp[2*q],     make_float2(v.x, v.y), a2);
            a2 = ffma2(bp[2*q + 1], make_float2(v.z, v.w), a2);
        }
        const float xd = a2.x + a2.y + s_bd[0];
        res.w = fmaxf(xd, 0.f) + log1pf(expf(-fabsf(xd)));
    }

    ((float4*)out)[i] = res;
}

extern "C" void kernel_launch(void* const* d_in, const int* in_sizes, int n_in,
                              void* d_out, int out_size) {
    (void)in_sizes; (void)n_in; (void)out_size;
    const float*  pos = (const float*)d_in[0];
    const float*  dir = (const float*)d_in[1];
    const float2* tab = (const float2*)d_in[2];
    const float *w0 = (const float*)d_in[3],  *b0 = (const float*)d_in[4];
    const float *w1 = (const float*)d_in[5],  *b1 = (const float*)d_in[6];
    const float *w2 = (const float*)d_in[7],  *b2 = (const float*)d_in[8];
    const float *wr = (const float*)d_in[9],  *br = (const float*)d_in[10];
    const float *wc = (const float*)d_in[11], *bc = (const float*)d_in[12];
    const float *wd = (const float*)d_in[13], *bd = (const float*)d_in[14];
    float* out = (float*)d_out;

    cudaFuncSetAttribute(ngp_fused_kernel,
                         cudaFuncAttributeMaxDynamicSharedMemorySize, SMEM_BYTES);
    ngp_fused_kernel<<<N_PTS / BLOCK, BLOCK, SMEM_BYTES>>>(
        pos, dir, tab, w0, b0, w1, b1, w2, b2, wr, br, wc, bc, wd, bd, out);
}

// round 4
// speedup vs baseline: 1.2063x; 1.1310x over previous
#include <cuda_runtime.h>

#define N_PTS   524288
#define TBITS   19
#define TSIZE   (1u << TBITS)
#define TMASK   (TSIZE - 1u)
#define BLOCK   256
#define PPB     128            // points per block
#define AS      65             // activation row stride (floats): 64 wide + odd pad
#define W_FLOATS 13576
#define SMEM_FLOATS (W_FLOATS + PPB * AS)
#define SMEM_BYTES  (SMEM_FLOATS * 4)

// Packed dual-FMA on float2 (sm_103a f32x2 pipe)
__device__ __forceinline__ float2 ffma2(float2 a, float2 b, float2 c) {
    float2 d;
    asm("fma.rn.f32x2 %0, %1, %2, %3;"
        : "=l"(reinterpret_cast<unsigned long long&>(d))
        : "l"(reinterpret_cast<unsigned long long&>(a)),
          "l"(reinterpret_cast<unsigned long long&>(b)),
          "l"(reinterpret_cast<unsigned long long&>(c)));
    return d;
}

__constant__ float c_scale[16] = {
    16.f, 21.f, 27.f, 36.f, 48.f, 64.f, 84.f, 111.f,
    147.f, 194.f, 256.f, 337.f, 445.f, 588.f, 776.f, 1024.f
};

__global__ __launch_bounds__(BLOCK, 2) void ngp_fused_kernel(
    const float*  __restrict__ pos,  const float* __restrict__ dir,
    const float2* __restrict__ tab,
    const float* __restrict__ w0, const float* __restrict__ b0,
    const float* __restrict__ w1, const float* __restrict__ b1,
    const float* __restrict__ w2, const float* __restrict__ b2,
    const float* __restrict__ wr, const float* __restrict__ br,
    const float* __restrict__ wc, const float* __restrict__ bc,
    const float* __restrict__ wd, const float* __restrict__ bd,
    float* __restrict__ out)
{
    extern __shared__ float sm[];
    float4* s_w0  = (float4*)(sm + 0);      // [64 out][8  q]
    float4* s_w1  = (float4*)(sm + 2048);   // [64 out][16 q]
    float4* s_w2  = (float4*)(sm + 6144);   // [64 out][16 q]
    float4* s_wrb = (float4*)(sm + 10240);  // [32 out][16 q]  (wr rows 27..90)
    float4* s_wrd = (float4*)(sm + 12288);  // [32 out][7  q]  (wr rows 0..26 + pad)
    float4* s_wc  = (float4*)(sm + 13184);  // [3][8 q]
    float4* s_wd  = (float4*)(sm + 13280);  // [16 q]
    float*  s_b0  = sm + 13344;
    float*  s_b1  = sm + 13408;
    float*  s_b2  = sm + 13472;
    float*  s_br  = sm + 13536;
    float*  s_bc  = sm + 13568;
    float*  s_bd  = sm + 13572;
    float*  buf   = sm + W_FLOATS;          // [128][65] activation buffer

    const int t = threadIdx.x;
    for (int k = t; k < 64 * 8; k += BLOCK) {
        int o = k >> 3, q = k & 7;
        s_w0[k] = make_float4(w0[(4*q  )*64 + o], w0[(4*q+1)*64 + o],
                              w0[(4*q+2)*64 + o], w0[(4*q+3)*64 + o]);
    }
    for (int k = t; k < 64 * 16; k += BLOCK) {
        int o = k >> 4, q = k & 15;
        s_w1[k] = make_float4(w1[(4*q  )*64 + o], w1[(4*q+1)*64 + o],
                              w1[(4*q+2)*64 + o], w1[(4*q+3)*64 + o]);
        s_w2[k] = make_float4(w2[(4*q  )*64 + o], w2[(4*q+1)*64 + o],
                              w2[(4*q+2)*64 + o], w2[(4*q+3)*64 + o]);
    }
    for (int k = t; k < 32 * 16; k += BLOCK) {
        int o = k >> 4, q = k & 15;
        s_wrb[k] = make_float4(wr[(27+4*q  )*32 + o], wr[(27+4*q+1)*32 + o],
                               wr[(27+4*q+2)*32 + o], wr[(27+4*q+3)*32 + o]);
    }
    for (int k = t; k < 32 * 7; k += BLOCK) {
        int o = k / 7, q = k % 7;
        float a = wr[(4*q  )*32 + o];
        float b = wr[(4*q+1)*32 + o];
        float c = wr[(4*q+2)*32 + o];
        float d = (q == 6) ? 0.f : wr[(4*q+3)*32 + o];
        s_wrd[k] = make_float4(a, b, c, d);
    }
    for (int k = t; k < 3 * 8; k += BLOCK) {
        int c = k >> 3, q = k & 7;
        s_wc[k] = make_float4(wc[(4*q  )*3 + c], wc[(4*q+1)*3 + c],
                              wc[(4*q+2)*3 + c], wc[(4*q+3)*3 + c]);
    }
    for (int k = t; k < 16; k += BLOCK)
        s_wd[k] = make_float4(wd[4*k], wd[4*k+1], wd[4*k+2], wd[4*k+3]);
    for (int k = t; k < 64; k += BLOCK) { s_b0[k] = b0[k]; s_b1[k] = b1[k]; s_b2[k] = b2[k]; }
    for (int k = t; k < 32; k += BLOCK) s_br[k] = br[k];
    if (t < 3) s_bc[t] = bc[t];
    if (t == 0) s_bd[0] = bd[0];
    __syncthreads();

    const int pt = t & (PPB - 1);
    const int hf = t >> 7;                 // 0 or 1
    const int i  = blockIdx.x * PPB + pt;
    float* row = buf + pt * AS;

    const float px = pos[3 * i], py = pos[3 * i + 1], pz = pos[3 * i + 2];

    // ---------------- Hash encode: 8 interleaved levels per half -> row[0..31] ----
    #pragma unroll
    for (int j = 0; j < 8; j++) {
        const int l = 2 * j + hf;
        const float sc = c_scale[l];
        const float sx = px * sc, sy = py * sc, sz = pz * sc;
        const float fx = floorf(sx), fy = floorf(sy), fz = floorf(sz);
        const float ox = sx - fx, oy = sy - fy, oz = sz - fz;
        const unsigned hx0 = (unsigned)(int)fx;                 // prime = 1
        const unsigned hx1 = (unsigned)(int)ceilf(sx);
        const unsigned hy0 = (unsigned)(int)fy * 2654435761u;
        const unsigned hy1 = (unsigned)(int)ceilf(sy) * 2654435761u;
        const unsigned hz0 = (unsigned)(int)fz * 805459861u;
        const unsigned hz1 = (unsigned)(int)ceilf(sz) * 805459861u;
        const unsigned lvl = ((unsigned)l) << TBITS;
        const float wx0 = 1.f - ox, wy0 = 1.f - oy, wz0 = 1.f - oz;

        float2 a = make_float2(0.f, 0.f);
        #pragma unroll
        for (int p = 0; p < 4; p++) {
            const unsigned hyz = ((p & 1) ? hy1 : hy0) ^ ((p & 2) ? hz1 : hz0);
            const unsigned i0 = (hx0 ^ hyz) & TMASK;
            const unsigned i1 = (hx1 ^ hyz) & TMASK;
            const float4 q = __ldg((const float4*)(tab + ((i0 & ~1u) + lvl)));
            const float2 lo = make_float2(q.x, q.y);
            const float2 hi = make_float2(q.z, q.w);
            float2 e0 = (i0 & 1u) ? hi : lo;
            float2 e1;
            if (i1 == (i0 ^ 1u)) {
                e1 = (i0 & 1u) ? lo : hi;
            } else {
                e1 = __ldg(&tab[i1 + lvl]);
            }
            const float wyz = ((p & 1) ? oy : wy0) * ((p & 2) ? oz : wz0);
            const float w0f = wx0 * wyz, w1f = ox * wyz;
            a = ffma2(make_float2(w0f, w0f), e0, a);
            a = ffma2(make_float2(w1f, w1f), e1, a);
        }
        row[2 * l]     = a.x;
        row[2 * l + 1] = a.y;
    }
    __syncthreads();

    float act[64];
    float o32[32];

    // ---------------- Layer 0: 32 -> 64, relu (half computes 32 outputs) -------
    #pragma unroll
    for (int k = 0; k < 32; k++) act[k] = row[k];
    #pragma unroll
    for (int o = 0; o < 32; o++) {
        const int og = hf * 32 + o;
        float2 a = make_float2(0.f, 0.f);
        const float4* wrow = s_w0 + og * 8;
        #pragma unroll
        for (int q = 0; q < 8; q++) {
            const float4 v = wrow[q];
            a = ffma2(make_float2(act[4*q],   act[4*q+1]), make_float2(v.x, v.y), a);
            a = ffma2(make_float2(act[4*q+2], act[4*q+3]), make_float2(v.z, v.w), a);
        }
        o32[o] = fmaxf(a.x + a.y + s_b0[og], 0.f);
    }
    __syncthreads();                       // all reads of row done
    #pragma unroll
    for (int o = 0; o < 32; o++) row[hf * 32 + o] = o32[o];
    __syncthreads();                       // writes visible

    // ---------------- Layer 1: 64 -> 64, relu ----------------
    #pragma unroll
    for (int k = 0; k < 64; k++) act[k] = row[k];
    #pragma unroll
    for (int o = 0; o < 32; o++) {
        const int og = hf * 32 + o;
        float2 a = make_float2(0.f, 0.f);
        const float4* wrow = s_w1 + og * 16;
        #pragma unroll
        for (int q = 0; q < 16; q++) {
            const float4 v = wrow[q];
            a = ffma2(make_float2(act[4*q],   act[4*q+1]), make_float2(v.x, v.y), a);
            a = ffma2(make_float2(act[4*q+2], act[4*q+3]), make_float2(v.z, v.w), a);
        }
        o32[o] = fmaxf(a.x + a.y + s_b1[og], 0.f);
    }
    __syncthreads();
    #pragma unroll
    for (int o = 0; o < 32; o++) row[hf * 32 + o] = o32[o];
    __syncthreads();

    // ---------------- Layer 2: 64 -> 64, linear (base) ----------------
    #pragma unroll
    for (int k = 0; k < 64; k++) act[k] = row[k];
    #pragma unroll
    for (int o = 0; o < 32; o++) {
        const int og = hf * 32 + o;
        float2 a = make_float2(0.f, 0.f);
        const float4* wrow = s_w2 + og * 16;
        #pragma unroll
        for (int q = 0; q < 16; q++) {
            const float4 v = wrow[q];
            a = ffma2(make_float2(act[4*q],   act[4*q+1]), make_float2(v.x, v.y), a);
            a = ffma2(make_float2(act[4*q+2], act[4*q+3]), make_float2(v.z, v.w), a);
        }
        o32[o] = a.x + a.y + s_b2[og];
    }
    __syncthreads();
    #pragma unroll
    for (int o = 0; o < 32; o++) row[hf * 32 + o] = o32[o];
    __syncthreads();

    // ---------------- bp = row[0..63] ----------------
    #pragma unroll
    for (int k = 0; k < 64; k++) act[k] = row[k];   // bp (stays live for density)

    const float dx = dir[3 * i], dy = dir[3 * i + 1], dz = dir[3 * i + 2];
    float dvec[28];
    {
        const float fr[4] = {1.f, 2.5198421f, 6.3496042f, 16.f};
        const float tx = 6.2831855f * dx, ty = 6.2831855f * dy, tz = 6.2831855f * dz;
        #pragma unroll
        for (int k = 0; k < 4; k++) {
            sincosf(tx * fr[k], &dvec[0 + k],  &dvec[12 + k]);
            sincosf(ty * fr[k], &dvec[4 + k],  &dvec[16 + k]);
            sincosf(tz * fr[k], &dvec[8 + k],  &dvec[20 + k]);
        }
        dvec[24] = dx; dvec[25] = dy; dvec[26] = dz; dvec[27] = 0.f;
    }

    // rgbh: this half computes 16 of 32 outputs
    float r16[16];
    #pragma unroll
    for (int o = 0; o < 16; o++) {
        const int og = hf * 16 + o;
        float acc = s_br[og];
        const float4* wdrow = s_wrd + og * 7;
        #pragma unroll
        for (int q = 0; q < 7; q++) {
            const float4 v = wdrow[q];
            acc = fmaf(dvec[4*q],   v.x, acc);
            acc = fmaf(dvec[4*q+1], v.y, acc);
            acc = fmaf(dvec[4*q+2], v.z, acc);
            acc = fmaf(dvec[4*q+3], v.w, acc);
        }
        float2 a2 = make_float2(0.f, 0.f);
        const float4* wbrow = s_wrb + og * 16;
        #pragma unroll
        for (int q = 0; q < 16; q++) {
            const float4 v = wbrow[q];
            a2 = ffma2(make_float2(act[4*q],   act[4*q+1]), make_float2(v.x, v.y), a2);
            a2 = ffma2(make_float2(act[4*q+2], act[4*q+3]), make_float2(v.z, v.w), a2);
        }
        r16[o] = acc + a2.x + a2.y;
    }
    __syncthreads();
    #pragma unroll
    for (int o = 0; o < 16; o++) row[hf * 16 + o] = r16[o];
    __syncthreads();

    if (hf == 0) {
        // rgb = sigmoid(rgbh @ wc + bc)
        float rg[32];
        #pragma unroll
        for (int k = 0; k < 32; k++) rg[k] = row[k];
        #pragma unroll
        for (int c = 0; c < 3; c++) {
            float acc = s_bc[c];
            const float4* wcrow = s_wc + c * 8;
            #pragma unroll
            for (int q = 0; q < 8; q++) {
                const float4 v = wcrow[q];
                acc = fmaf(rg[4*q],   v.x, acc);
                acc = fmaf(rg[4*q+1], v.y, acc);
                acc = fmaf(rg[4*q+2], v.z, acc);
                acc = fmaf(rg[4*q+3], v.w, acc);
            }
            out[4 * i + c] = 1.f / (1.f + expf(-acc));
        }
    } else {
        // density = softplus(bp @ wd + bd)
        float2 a2 = make_float2(0.f, 0.f);
        #pragma unroll
        for (int q = 0; q < 16; q++) {
            const float4 v = s_wd[q];
            a2 = ffma2(make_float2(act[4*q],   act[4*q+1]), make_float2(v.x, v.y), a2);
            a2 = ffma2(make_float2(act[4*q+2], act[4*q+3]), make_float2(v.z, v.w), a2);
        }
        const float xd = a2.x + a2.y + s_bd[0];
        out[4 * i + 3] = fmaxf(xd, 0.f) + log1pf(expf(-fabsf(xd)));
    }
}

extern "C" void kernel_launch(void* const* d_in, const int* in_sizes, int n_in,
                              void* d_out, int out_size) {
    (void)in_sizes; (void)n_in; (void)out_size;
    const float*  pos = (const float*)d_in[0];
    const float*  dir = (const float*)d_in[1];
    const float2* tab = (const float2*)d_in[2];
    const float *w0 = (const float*)d_in[3],  *b0 = (const float*)d_in[4];
    const float *w1 = (const float*)d_in[5],  *b1 = (const float*)d_in[6];
    const float *w2 = (const float*)d_in[7],  *b2 = (const float*)d_in[8];
    const float *wr = (const float*)d_in[9],  *br = (const float*)d_in[10];
    const float *wc = (const float*)d_in[11], *bc = (const float*)d_in[12];
    const float *wd = (const float*)d_in[13], *bd = (const float*)d_in[14];
    float* out = (float*)d_out;

    cudaFuncSetAttribute(ngp_fused_kernel,
                         cudaFuncAttributeMaxDynamicSharedMemorySize, SMEM_BYTES);
    ngp_fused_kernel<<<N_PTS / PPB, BLOCK, SMEM_BYTES>>>(
        pos, dir, tab, w0, b0, w1, b1, w2, b2, wr, br, wc, bc, wd, bd, out);
}